// round 7
// baseline (speedup 1.0000x reference)
#include <cuda_runtime.h>
#include <cstdint>

#define BB 512
#define TT 8192
#define KW 5
#define NTH 128
#define WPB 4
#define CLF4 16               // float4s per lane chunk (64 steps)
#define WARP_F4 512           // float4s per warp slice (2048 steps)
#define HALO_F4 48            // 192-step speculative warmup halo
#define SLICE_F4 (WARP_F4 + HALO_F4)   // 560
#define GRID 152

// XOR swizzle on float4 index: for lane-stride-16 reads (warm/real) and
// contiguous-32 accesses (cp.async dst, writeback), every 8-lane phase hits
// 8 distinct 16B bank-quads -> conflict-free.
#define QS(u) ((u) ^ ((((unsigned)(u)) >> 4) & 7))

#define SMEM_DYN (WPB * 2 * 3 * SLICE_F4 * 16)   // 215,040 bytes

__device__ __forceinline__ uint32_t smem_u32(const void* p) {
    uint32_t a;
    asm("{ .reg .u64 t; cvta.to.shared.u64 t, %1; cvt.u32.u64 %0, t; }"
        : "=r"(a) : "l"(p));
    return a;
}

__device__ __forceinline__ float fset_ge1(float c) {
    float r;
    asm("set.ge.f32.f32 %0, %1, 0f3F800000;" : "=f"(r) : "f"(c));
    return r;
}

__device__ __forceinline__ void insert5(float kk[KW], float x) {
    kk[4] = fmaxf(kk[4], x);
#pragma unroll
    for (int j = 4; j >= 1; j--) {
        float hi = fmaxf(kk[j - 1], kk[j]);
        float lo = fminf(kk[j - 1], kk[j]);
        kk[j - 1] = hi; kk[j] = lo;
    }
}

// Exact XLA step semantics: c = RN(RN(d*v)+x); spike = (c>=1); v' = c - spike
// (c-1 exact by Sterbenz for c in [1,2)).
#define WSTEP(xa, xp, xb) do {                        \
    float c0 = __fadd_rn(__fmul_rn(d0, v0), (xa));    \
    float c1 = __fadd_rn(__fmul_rn(d1, v1), (xp));    \
    float c2 = __fadd_rn(__fmul_rn(d2, v2), (xb));    \
    v0 = __fadd_rn(c0, -fset_ge1(c0));                \
    v1 = __fadd_rn(c1, -fset_ge1(c1));                \
    v2 = __fadd_rn(c2, -fset_ge1(c2));                \
} while (0)

__device__ __forceinline__ float rstep(float& v0, float& v1, float& v2,
                                       float d0, float d1, float d2,
                                       float w0, float w1, float w2,
                                       float xa, float xp, float xb) {
    float c0 = __fadd_rn(__fmul_rn(d0, v0), xa);
    float c1 = __fadd_rn(__fmul_rn(d1, v1), xp);
    float c2 = __fadd_rn(__fmul_rn(d2, v2), xb);
    float s0 = fset_ge1(c0), s1 = fset_ge1(c1), s2 = fset_ge1(c2);
    v0 = __fadd_rn(c0, -s0);
    v1 = __fadd_rn(c1, -s1);
    v2 = __fadd_rn(c2, -s2);
    return __fmaf_rn(s2, w2, __fmaf_rn(s1, w1, __fmul_rn(s0, w0)));
}

// Issue all cp.asyncs for one warp-slice of one row (no commit).
__device__ __forceinline__ void issue_loads(
    const float4* __restrict__ gA, const float4* __restrict__ gP,
    const float4* __restrict__ gB, int row, int w, int l, float4* buf)
{
    long rowf4 = (long)row * (TT / 4);
    const float4* A = gA + rowf4;
    const float4* P = gP + rowf4;
    const float4* B = gB + rowf4;
    uint32_t a_u = smem_u32(buf);
    uint32_t p_u = smem_u32(buf + SLICE_F4);
    uint32_t b_u = smem_u32(buf + 2 * SLICE_F4);
    int g0 = w * WARP_F4 - HALO_F4;
#pragma unroll
    for (int it = 0; it < (SLICE_F4 + 31) / 32; it++) {
        int j = it * 32 + l;
        if (j >= SLICE_F4) break;
        int src = g0 + j;
        uint32_t off = (uint32_t)QS(j) * 16u;
        if (src >= 0) {
            asm volatile("cp.async.ca.shared.global [%0], [%1], 16;"
                         :: "r"(a_u + off), "l"(A + src));
            asm volatile("cp.async.ca.shared.global [%0], [%1], 16;"
                         :: "r"(p_u + off), "l"(P + src));
            asm volatile("cp.async.ca.shared.global [%0], [%1], 16;"
                         :: "r"(b_u + off), "l"(B + src));
        } else {
            // row-start halo: zeros are EXACT (v stays 0 through zero prefix)
            float4 z = make_float4(0.f, 0.f, 0.f, 0.f);
            buf[QS(j)] = z;
            buf[SLICE_F4 + QS(j)] = z;
            buf[2 * SLICE_F4 + QS(j)] = z;
        }
    }
}

__global__ void __launch_bounds__(NTH, 1) fused_kernel(
    const float* __restrict__ amp, const float* __restrict__ pitch,
    const float* __restrict__ boundary, const float* __restrict__ decay,
    const float* __restrict__ weights, float* __restrict__ out)
{
    extern __shared__ float4 sm4[];
    __shared__ float mk[WPB * KW];
    __shared__ float s_den;

    int tid = threadIdx.x;
    int w   = tid >> 5;
    int l   = tid & 31;

    float d0 = __ldg(decay),   d1 = __ldg(decay + 1),   d2 = __ldg(decay + 2);
    float w0 = __ldg(weights), w1 = __ldg(weights + 1), w2 = __ldg(weights + 2);

    const float4* gA = (const float4*)amp;
    const float4* gP = (const float4*)pitch;
    const float4* gB = (const float4*)boundary;

    float4* buf0 = sm4 + (w * 2 + 0) * 3 * SLICE_F4;
    float4* buf1 = sm4 + (w * 2 + 1) * 3 * SLICE_F4;

    int rows[4]; int nrows = 0;
    for (int r = blockIdx.x; r < BB; r += GRID) rows[nrows++] = r;

    // ---- prologue: prefetch rows 0 and 1 ----
    issue_loads(gA, gP, gB, rows[0], w, l, buf0);
    asm volatile("cp.async.commit_group;" ::: "memory");
    if (nrows > 1) issue_loads(gA, gP, gB, rows[1], w, l, buf1);
    asm volatile("cp.async.commit_group;" ::: "memory");

    for (int i = 0; i < nrows; i++) {
        int row = rows[i];
        float4* buf = (i & 1) ? buf1 : buf0;
        float4* SA = buf;
        float4* SP = buf + SLICE_F4;
        float4* SB = buf + 2 * SLICE_F4;

        // wait until at most 1 group pending -> group for this row is done
        asm volatile("cp.async.wait_group 1;" ::: "memory");
        __syncwarp();

        // ---- warmup: 192 steps (48 f4) ----
        float v0 = 0.f, v1 = 0.f, v2 = 0.f;
        int ub = CLF4 * l;
#pragma unroll 4
        for (int j = 0; j < HALO_F4; j++) {
            int u = QS(ub + j);
            float4 xa = SA[u], xp = SP[u], xb = SB[u];
            WSTEP(xa.x, xp.x, xb.x);
            WSTEP(xa.y, xp.y, xb.y);
            WSTEP(xa.z, xp.z, xb.z);
            WSTEP(xa.w, xp.w, xb.w);
        }
        __syncwarp();   // all warm reads done before any stash overwrites

        // ---- real chunk: 64 steps; stash vals in place; inline top-5 ----
        float kk[KW];
#pragma unroll
        for (int j = 0; j < KW; j++) kk[j] = -3.0e38f;
        int t0 = w * (WARP_F4 * 4) + l * (CLF4 * 4);

#pragma unroll 4
        for (int j = 0; j < CLF4; j++) {
            int u = QS(ub + HALO_F4 + j);
            float4 xa = SA[u], xp = SP[u], xb = SB[u];
            float4 val;
            val.x = rstep(v0, v1, v2, d0, d1, d2, w0, w1, w2, xa.x, xp.x, xb.x);
            val.y = rstep(v0, v1, v2, d0, d1, d2, w0, w1, w2, xa.y, xp.y, xb.y);
            val.z = rstep(v0, v1, v2, d0, d1, d2, w0, w1, w2, xa.z, xp.z, xb.z);
            val.w = rstep(v0, v1, v2, d0, d1, d2, w0, w1, w2, xa.w, xp.w, xb.w);
            SA[u] = val;   // same-lane same-address overwrite: safe

            float base = -(float)(t0 + 4 * j);
            float k0 = __fmaf_rn(val.x, 8192.f, base);
            float k1 = __fmaf_rn(val.y, 8192.f, base - 1.f);
            float k2 = __fmaf_rn(val.z, 8192.f, base - 2.f);
            float k3 = __fmaf_rn(val.w, 8192.f, base - 3.f);
            float m = fmaxf(fmaxf(k0, k1), fmaxf(k2, k3));
            if (m > kk[4]) { insert5(kk, k0); insert5(kk, k1);
                             insert5(kk, k2); insert5(kk, k3); }
        }

        // ---- warp butterfly merge (no barriers), then 2-barrier block merge ----
#pragma unroll
        for (int s = 16; s >= 1; s >>= 1) {
            float ok[KW];
#pragma unroll
            for (int j = 0; j < KW; j++) ok[j] = __shfl_xor_sync(0xFFFFFFFFu, kk[j], s);
#pragma unroll
            for (int j = 0; j < KW; j++) if (ok[j] > kk[4]) insert5(kk, ok[j]);
        }
        if (l == 0) {
#pragma unroll
            for (int j = 0; j < KW; j++) mk[w * KW + j] = kk[j];
        }
        __syncthreads();

        if (tid == 0) {
#pragma unroll
            for (int j = 0; j < KW; j++) kk[j] = mk[j];
#pragma unroll
            for (int s = 1; s < WPB; s++)
#pragma unroll
                for (int j = 0; j < KW; j++) {
                    float x = mk[s * KW + j];
                    if (x > kk[4]) insert5(kk, x);
                }
            float vmax = ceilf(kk[0] * (1.0f / 8192.0f));   // exact: integer counts
            float den  = __fadd_rn(vmax, 1e-6f);
            float ssum = 0.f;
            float* oi = out + BB + (long)BB * TT + row * KW;
#pragma unroll
            for (int j = 0; j < KW; j++) {
                float vj = ceilf(kk[j] * (1.0f / 8192.0f));
                float ij = __fmaf_rn(vj, 8192.0f, -kk[j]);  // exact integer index
                oi[j] = ij;
                ssum = __fadd_rn(ssum, vj / den);
            }
            float avg = ssum * 0.2f;
            out[row] = 0.5f + 2.0f * tanhf(1.8f * avg);
            s_den = den;
        }
        __syncthreads();

        // ---- writeback: coalesced float4 stores of normalized sal ----
        float inv = 1.0f / s_den;
        float4* go = (float4*)(out + BB) + (long)row * (TT / 4) + w * WARP_F4;
#pragma unroll 4
        for (int it = 0; it < WARP_F4 / 32; it++) {
            int o = 32 * it + l;
            float4 v = SA[QS(HALO_F4 + o)];
            go[o] = make_float4(v.x * inv, v.y * inv, v.z * inv, v.w * inv);
        }

        // ---- prefetch row i+2 into the buffer just consumed ----
        if (i + 2 < nrows) issue_loads(gA, gP, gB, rows[i + 2], w, l, buf);
        asm volatile("cp.async.commit_group;" ::: "memory");
    }
}

extern "C" void kernel_launch(void* const* d_in, const int* in_sizes, int n_in,
                              void* d_out, int out_size) {
    const float* amp      = (const float*)d_in[0];
    const float* pitch    = (const float*)d_in[1];
    const float* boundary = (const float*)d_in[2];
    const float* decay    = (const float*)d_in[3];
    const float* weights  = (const float*)d_in[4];
    float* out = (float*)d_out;

    cudaFuncSetAttribute(fused_kernel,
                         cudaFuncAttributeMaxDynamicSharedMemorySize, SMEM_DYN);
    // Output layout: [mu (512)] [sal (512*8192)] [topk_idx (512*5) as f32]
    fused_kernel<<<GRID, NTH, SMEM_DYN>>>(amp, pitch, boundary, decay, weights, out);
}

// round 8
// speedup vs baseline: 1.3762x; 1.3762x over previous
#include <cuda_runtime.h>
#include <cstdint>

#define BB 512
#define TT 8192
#define KW 5
#define NTH 192               // 6 warps: (channel, half) pairs
#define HALO_F4 48            // 192-step speculative warmup halo
#define HALF_F4 1024          // float4s per half-row (4096 steps)
#define SLICE_F4 (HALF_F4 + HALO_F4)   // 1072
#define CLF4 32               // float4s per lane (128 steps)

// XOR swizzle on float4 index (lane stride 32 f4): every 8-lane phase hits
// 8 distinct 16B bank-quads for both stride-32-lane and contiguous patterns.
#define QS(u) ((u) ^ ((((unsigned)(u)) >> 5) & 7))

#define SMEM_DYN (6 * SLICE_F4 * 16)   // 102,912 bytes -> 2 blocks/SM

__device__ __forceinline__ uint32_t smem_u32(const void* p) {
    uint32_t a;
    asm("{ .reg .u64 t; cvta.to.shared.u64 t, %1; cvt.u32.u64 %0, t; }"
        : "=r"(a) : "l"(p));
    return a;
}

__device__ __forceinline__ float fset_ge1(float c) {
    float r;
    asm("set.ge.f32.f32 %0, %1, 0f3F800000;" : "=f"(r) : "f"(c));
    return r;
}

__device__ __forceinline__ void insert5(float kk[KW], float x) {
    kk[4] = fmaxf(kk[4], x);
#pragma unroll
    for (int j = 4; j >= 1; j--) {
        float hi = fmaxf(kk[j - 1], kk[j]);
        float lo = fminf(kk[j - 1], kk[j]);
        kk[j - 1] = hi; kk[j] = lo;
    }
}

// Exact XLA step: c = RN(RN(d*v)+x); s = (c>=1); v' = c - s
// (c-1 exact by Sterbenz for c in [1,2)). Single channel per lane.
__device__ __forceinline__ float sstep(float& v, float d, float x) {
    float c = __fadd_rn(__fmul_rn(d, v), x);
    float s = fset_ge1(c);
    v = __fadd_rn(c, -s);
    return s;
}

__global__ void __launch_bounds__(NTH, 2) fused_kernel(
    const float* __restrict__ amp, const float* __restrict__ pitch,
    const float* __restrict__ boundary, const float* __restrict__ decay,
    const float* __restrict__ weights, float* __restrict__ out)
{
    extern __shared__ float4 sm4[];
    __shared__ float mk[6 * KW];
    __shared__ float s_den;

    int row = blockIdx.x;
    int tid = threadIdx.x;
    int w   = tid >> 5;        // 0..5
    int l   = tid & 31;
    int ch  = w >> 1;          // channel 0..2
    int h   = w & 1;           // half-row 0/1
    long rowf4 = (long)row * (TT / 4);

    float d  = __ldg(decay + ch);
    float w0 = __ldg(weights), w1 = __ldg(weights + 1), w2 = __ldg(weights + 2);

    const float* chp = (ch == 0) ? amp : (ch == 1) ? pitch : boundary;
    const float4* g  = (const float4*)chp + rowf4;

    float4* S = sm4 + w * SLICE_F4;
    uint32_t s_u = smem_u32(S);

    // ---- load own (channel, half) slice via cp.async ----
    {
        int g0 = h * HALF_F4 - HALO_F4;
#pragma unroll
        for (int it = 0; it < (SLICE_F4 + 31) / 32; it++) {
            int j = it * 32 + l;
            if (j >= SLICE_F4) break;
            int src = g0 + j;
            uint32_t off = (uint32_t)QS(j) * 16u;
            if (src >= 0) {
                asm volatile("cp.async.ca.shared.global [%0], [%1], 16;"
                             :: "r"(s_u + off), "l"(g + src));
            } else {
                // row-start halo: zeros are EXACT (v stays 0 through zero prefix)
                S[QS(j)] = make_float4(0.f, 0.f, 0.f, 0.f);
            }
        }
        asm volatile("cp.async.wait_all;" ::: "memory");
        __syncwarp();
    }

    // ---- warmup: 192 steps (48 f4), state only ----
    float v = 0.f;
    int ub = CLF4 * l;         // lane's warm start (48 f4 before real chunk)
#pragma unroll 8
    for (int j = 0; j < HALO_F4; j++) {
        int u = QS(ub + j);
        float4 x = S[u];
        sstep(v, d, x.x); sstep(v, d, x.y); sstep(v, d, x.z); sstep(v, d, x.w);
    }
    __syncwarp();   // all warm reads done before any stash overwrites

    // ---- real chunk: 128 steps; stash raw spikes in place ----
#pragma unroll 8
    for (int j = 0; j < CLF4; j++) {
        int u = QS(ub + HALO_F4 + j);
        float4 x = S[u];
        float4 s;
        s.x = sstep(v, d, x.x);
        s.y = sstep(v, d, x.y);
        s.z = sstep(v, d, x.z);
        s.w = sstep(v, d, x.w);
        S[u] = s;   // same-lane same-address overwrite: safe
    }
    __syncthreads();

    // ---- pass A: sum channels, stash unnormalized sal, per-thread top-5 ----
    float kk[KW];
#pragma unroll
    for (int j = 0; j < KW; j++) kk[j] = -3.0e38f;

    float4* S0 = sm4;                      // ch0 slices (h at +SLICE_F4)
    float4* S1 = sm4 + 2 * SLICE_F4;
    float4* S2 = sm4 + 4 * SLICE_F4;
    for (int i = tid; i < TT / 4; i += NTH) {
        int hh  = i >> 10;
        int off = hh * SLICE_F4;
        int u   = QS(HALO_F4 + (i & 1023));
        float4 a = S0[off + u], p = S1[off + u], q = S2[off + u];
        float4 val;
        val.x = __fmaf_rn(w2, q.x, __fmaf_rn(w1, p.x, __fmul_rn(w0, a.x)));
        val.y = __fmaf_rn(w2, q.y, __fmaf_rn(w1, p.y, __fmul_rn(w0, a.y)));
        val.z = __fmaf_rn(w2, q.z, __fmaf_rn(w1, p.z, __fmul_rn(w0, a.z)));
        val.w = __fmaf_rn(w2, q.w, __fmaf_rn(w1, p.w, __fmul_rn(w0, a.w)));
        S0[off + u] = val;                 // stash sums into ch0 slice

        float base = -(float)(4 * i);
        float k0 = __fmaf_rn(val.x, 8192.f, base);
        float k1 = __fmaf_rn(val.y, 8192.f, base - 1.f);
        float k2 = __fmaf_rn(val.z, 8192.f, base - 2.f);
        float k3 = __fmaf_rn(val.w, 8192.f, base - 3.f);
        float m = fmaxf(fmaxf(k0, k1), fmaxf(k2, k3));
        if (m > kk[4]) { insert5(kk, k0); insert5(kk, k1);
                         insert5(kk, k2); insert5(kk, k3); }
    }

    // ---- merge: warp butterfly, then thread 0 across 6 warps ----
#pragma unroll
    for (int s = 16; s >= 1; s >>= 1) {
        float ok[KW];
#pragma unroll
        for (int j = 0; j < KW; j++) ok[j] = __shfl_xor_sync(0xFFFFFFFFu, kk[j], s);
#pragma unroll
        for (int j = 0; j < KW; j++) if (ok[j] > kk[4]) insert5(kk, ok[j]);
    }
    if (l == 0) {
#pragma unroll
        for (int j = 0; j < KW; j++) mk[w * KW + j] = kk[j];
    }
    __syncthreads();

    if (tid == 0) {
#pragma unroll
        for (int j = 0; j < KW; j++) kk[j] = mk[j];
#pragma unroll
        for (int s = 1; s < 6; s++)
#pragma unroll
            for (int j = 0; j < KW; j++) {
                float x = mk[s * KW + j];
                if (x > kk[4]) insert5(kk, x);
            }
        float vmax = ceilf(kk[0] * (1.0f / 8192.0f));   // exact: integer counts
        float den  = __fadd_rn(vmax, 1e-6f);
        float ssum = 0.f;
        float* oi = out + BB + (long)BB * TT + row * KW;
#pragma unroll
        for (int j = 0; j < KW; j++) {
            float vj = ceilf(kk[j] * (1.0f / 8192.0f));
            float ij = __fmaf_rn(vj, 8192.0f, -kk[j]);  // exact integer index
            oi[j] = ij;
            ssum = __fadd_rn(ssum, vj / den);
        }
        float avg = ssum * 0.2f;
        out[row] = 0.5f + 2.0f * tanhf(1.8f * avg);
        s_den = den;
    }
    __syncthreads();

    // ---- pass B: normalize + coalesced float4 stores ----
    float inv = 1.0f / s_den;
    float4* go = (float4*)(out + BB) + rowf4;
    for (int i = tid; i < TT / 4; i += NTH) {
        int hh  = i >> 10;
        int u   = QS(HALO_F4 + (i & 1023)) + hh * SLICE_F4;
        float4 v4 = S0[u];
        go[i] = make_float4(v4.x * inv, v4.y * inv, v4.z * inv, v4.w * inv);
    }
}

extern "C" void kernel_launch(void* const* d_in, const int* in_sizes, int n_in,
                              void* d_out, int out_size) {
    const float* amp      = (const float*)d_in[0];
    const float* pitch    = (const float*)d_in[1];
    const float* boundary = (const float*)d_in[2];
    const float* decay    = (const float*)d_in[3];
    const float* weights  = (const float*)d_in[4];
    float* out = (float*)d_out;

    cudaFuncSetAttribute(fused_kernel,
                         cudaFuncAttributeMaxDynamicSharedMemorySize, SMEM_DYN);
    // Output layout: [mu (512)] [sal (512*8192)] [topk_idx (512*5) as f32]
    fused_kernel<<<BB, NTH, SMEM_DYN>>>(amp, pitch, boundary, decay, weights, out);
}